// round 11
// baseline (speedup 1.0000x reference)
#include <cuda_runtime.h>
#include <math.h>

// HG2Vec fused loss, v11: fully pipelined hybrid.
//   shared rows (t=W_out[pu], f=W_in[iv], deduped 5x) : depth-3 cp.async SMEM
//     pipeline, prefetch 2 positions ahead, PRODUCE at top of iteration,
//     ONE __syncthreads per position.
//   private rows (a=W_in[pv], b=W_out[pv], per warp)  : chunk-level register
//     double-buffer (X/Y, 4 rows each): chunk j+1 loads issue before chunk j
//     FMAs; next position's chunk0 loads before the butterfly. No load->use
//     back-to-back anywhere in steady state.
// 5 warps/CTA (warp w owns contexts 2w,2w+1), 14 accumulators, scattered
// 16-value warp reduction (31 shfl), fast softplus (MUFU).
// __launch_bounds__(160,4): 4 CTAs/SM (reg cap 96; est ~88), grid 592.
// Last-block-done deterministic reduction, ticket self-resets (graph-safe).

#define DIM       300
#define ROWBYTES  1200
#define NPOS      16384           // B*L
#define GRID      592             // 148 SMs * 4 resident CTAs
#define THREADS   160             // 5 warps = 1 position
#define SHROWS    7               // t + f[0..5]
#define SHBUF     (SHROWS * ROWBYTES)   // 8400 B per stage
#define NCPY      (SHROWS * 75)         // 525 16B copies per position

__device__ float        g_partial[GRID];
__device__ unsigned int g_ticket = 0;

#define CP_ASYNC16(DST, SRC) \
    asm volatile("cp.async.cg.shared.global [%0], [%1], 16;" :: "r"(DST), "l"(SRC) : "memory")
#define CP_COMMIT()  asm volatile("cp.async.commit_group;" ::: "memory")
#define CP_WAIT1()   asm volatile("cp.async.wait_group 1;" ::: "memory")

// load 4 private rows' chunk at byte offset JB into buffer R (a0..b1 fields)
#define AB_LOAD(R, JB)                                                       \
    do {                                                                     \
        R##a0 = *(const float4*)(Win_b  + pvo0 + (JB));                      \
        R##a1 = *(const float4*)(Win_b  + pvo1 + (JB));                      \
        R##b0 = *(const float4*)(Wout_b + pvo0 + (JB));                      \
        R##b1 = *(const float4*)(Wout_b + pvo1 + (JB));                      \
    } while (0)

// accumulate one chunk: t/f from SMEM tile tf, a/b from buffer R
#define TF_CHUNK(R, JB)                                                      \
    do {                                                                     \
        const float4 t4_ = *(const float4*)(tf + (JB));                      \
        sc0 += R##a0.x * t4_.x + R##a0.y * t4_.y                             \
             + R##a0.z * t4_.z + R##a0.w * t4_.w;                            \
        sc1 += R##a1.x * t4_.x + R##a1.y * t4_.y                             \
             + R##a1.z * t4_.z + R##a1.w * t4_.w;                           \
        _Pragma("unroll")                                                    \
        for (int i_ = 0; i_ < 6; i_++) {                                     \
            const float4 f_ =                                                \
                *(const float4*)(tf + (1 + i_) * ROWBYTES + (JB));           \
            ai[i_]     += R##b0.x * f_.x + R##b0.y * f_.y                    \
                        + R##b0.z * f_.z + R##b0.w * f_.w;                   \
            ai[6 + i_] += R##b1.x * f_.x + R##b1.y * f_.y                    \
                        + R##b1.z * f_.z + R##b1.w * f_.w;                   \
        }                                                                    \
    } while (0)

// stage {pu, iv[0..5]} for position Q into SLOT (7 ints), clamped
#define STAGE_IDX(Q, SLOT)                                                   \
    do {                                                                     \
        if (tid < 7) {                                                       \
            const int ps_ = ((Q) < NPOS) ? (Q) : (NPOS - 1);                 \
            (SLOT)[tid] = (tid == 0) ? pos_u[ps_]                            \
                                     : info_v[ps_ * 6 + (tid - 1)];          \
        }                                                                    \
    } while (0)

// issue 525 cp.async 16B copies of the 7 shared rows into stage BUF
#define PRODUCE(BUF, SLOT)                                                   \
    do {                                                                     \
        const unsigned dbase_ = sbase + (unsigned)(BUF) * SHBUF;             \
        _Pragma("unroll")                                                    \
        for (int k_ = 0; k_ < 4; k_++) {                                     \
            const int n_ = tid + k_ * THREADS;                               \
            if (n_ < NCPY) {                                                 \
                const int row_ = n_ / 75;                                    \
                const int col_ = n_ - row_ * 75;                             \
                const long idx_ = (SLOT)[row_];                              \
                const char* src_ = ((row_ == 0) ? Wout_b : Win_b)            \
                                 + idx_ * ROWBYTES + col_ * 16;              \
                CP_ASYNC16(dbase_ + row_ * ROWBYTES + col_ * 16, src_);      \
            }                                                                \
        }                                                                    \
    } while (0)

// one iteration: X holds a/b chunk0 of p. Afterwards Y holds chunk0 of p+GRID.
#define ITER(X, Y)                                                           \
    do {                                                                     \
        const int pn_ = p + GRID;                                            \
        CP_WAIT1();                                                          \
        __syncthreads();         /* tile[cur] arrived + staged idx visible */ \
        const int s2_ = (cur >= 1) ? cur - 1 : cur + 2;   /* (cur+2)%3 */    \
        if (pn_ + GRID < NPOS) { PRODUCE(s2_, idxs[s2_]); }                  \
        CP_COMMIT();             /* keep group accounting uniform */         \
        STAGE_IDX(pn_ + 2 * GRID, idxs[cur]);                                \
        {                                                                    \
            const char* tf = tile[cur];                                      \
            float sc0 = 0.f, sc1 = 0.f;                                      \
            float ai[12];                                                    \
            _Pragma("unroll")                                                \
            for (int q_ = 0; q_ < 12; q_++) ai[q_] = 0.f;                    \
            AB_LOAD(Y, jb1);            /* chunk1 in flight */               \
            TF_CHUNK(X, jb0);           /* chunk0 */                         \
            if (lane < 11) AB_LOAD(X, jb2);  /* chunk2 in flight */          \
            TF_CHUNK(Y, jb1);           /* chunk1 */                         \
            {                                                                \
                const int ps_ = (pn_ < NPOS) ? pn_ : 0;                      \
                pvo0 = (unsigned)pos_v[ps_ * 10 + w * 2 + 0] * ROWBYTES;     \
                pvo1 = (unsigned)pos_v[ps_ * 10 + w * 2 + 1] * ROWBYTES;     \
            }                                                                \
            AB_LOAD(Y, jb0);            /* next pos chunk0 in flight */      \
            if (lane < 11) TF_CHUNK(X, jb2); /* chunk2 */                    \
            acc_loss += reduce_eval(sc0, sc1, ai, lane, t_pre, t_sgn, t_wt); \
        }                                                                    \
        cur = (cur == 2) ? 0 : cur + 1;                                      \
        p = pn_;                                                             \
    } while (0)

// scattered 16-value warp reduction (31 shfl) + in-place loss term.
__device__ __forceinline__ float reduce_eval(
    float sc0, float sc1, const float* ai, int lane,
    float t_pre, float t_sgn, float t_wt)
{
    float v0[8], v1[4], v2[2], v3;
    {
        float a, b;
        a = sc0   + __shfl_xor_sync(0xffffffffu, sc0,   16);
        b = ai[6] + __shfl_xor_sync(0xffffffffu, ai[6], 16);
        v0[0] = (lane & 16) ? b : a;
        a = sc1   + __shfl_xor_sync(0xffffffffu, sc1,   16);
        b = ai[7] + __shfl_xor_sync(0xffffffffu, ai[7], 16);
        v0[1] = (lane & 16) ? b : a;
#pragma unroll
        for (int q = 0; q < 4; q++) {
            a = ai[q]     + __shfl_xor_sync(0xffffffffu, ai[q],     16);
            b = ai[q + 8] + __shfl_xor_sync(0xffffffffu, ai[q + 8], 16);
            v0[2 + q] = (lane & 16) ? b : a;
        }
        a = ai[4] + __shfl_xor_sync(0xffffffffu, ai[4], 16);
        v0[6] = (lane & 16) ? 0.f : a;
        a = ai[5] + __shfl_xor_sync(0xffffffffu, ai[5], 16);
        v0[7] = (lane & 16) ? 0.f : a;
    }
#pragma unroll
    for (int q = 0; q < 4; q++) {
        const float a = v0[q]     + __shfl_xor_sync(0xffffffffu, v0[q],     8);
        const float b = v0[q + 4] + __shfl_xor_sync(0xffffffffu, v0[q + 4], 8);
        v1[q] = (lane & 8) ? b : a;
    }
#pragma unroll
    for (int q = 0; q < 2; q++) {
        const float a = v1[q]     + __shfl_xor_sync(0xffffffffu, v1[q],     4);
        const float b = v1[q + 2] + __shfl_xor_sync(0xffffffffu, v1[q + 2], 4);
        v2[q] = (lane & 4) ? b : a;
    }
    {
        const float a = v2[0] + __shfl_xor_sync(0xffffffffu, v2[0], 2);
        const float b = v2[1] + __shfl_xor_sync(0xffffffffu, v2[1], 2);
        v3 = (lane & 2) ? b : a;
    }
    v3 += __shfl_xor_sync(0xffffffffu, v3, 1);

    const float x = fminf(fmaxf(v3 * t_pre, -10.f), 10.f) * t_sgn;
    return __logf(1.f + __expf(-x)) * t_wt;
}

__global__ __launch_bounds__(THREADS, 4) void hg2vec_fused(
    const int*   __restrict__ pos_u,
    const int*   __restrict__ pos_v,
    const int*   __restrict__ info_v,
    const float* __restrict__ W_in,
    const float* __restrict__ W_out,
    const float* __restrict__ cmask,
    const float* __restrict__ sig_mask,
    const float* __restrict__ score_mask,
    float*       __restrict__ out)
{
    __shared__ __align__(16) char tile[3][SHBUF];
    __shared__ int   idxs[3][8];
    __shared__ float wloss[5];
    __shared__ bool  amLast;

    const int tid  = threadIdx.x;
    const int w    = tid >> 5;
    const int lane = tid & 31;
    const unsigned sbase = (unsigned)__cvta_generic_to_shared(&tile[0][0]);

    const char* __restrict__ Win_b  = (const char*)W_in;
    const char* __restrict__ Wout_b = (const char*)W_out;

    // ---- per-lane term coefficients; value index k = lane>>1 ----
    const int kk = lane >> 1;
    float t_pre = 1.f, t_sgn = 1.f, t_wt = 0.f;
    if (((lane & 1) == 0) && kk < 14) {
        if (kk < 2) { t_pre = cmask[w * 2 + kk]; t_sgn = 1.f; t_wt = 1.f; }
        else {
            const int i = (kk - 2) % 6;
            t_sgn = sig_mask[i];
            t_wt  = score_mask[i];
        }
    }

    const unsigned jb0 = (unsigned)lane * 16u;
    const unsigned jb1 = jb0 + 512u;
    const unsigned jb2 = jb0 + 1024u;   // lanes 0..10 only

    float acc_loss = 0.f;
    int p   = blockIdx.x;
    int cur = 0;

    // ---- prime: tiles for p (stage0) and p+GRID (stage1), idx for p+2G ----
    STAGE_IDX(p, idxs[0]);
    __syncthreads();
    PRODUCE(0, idxs[0]);
    CP_COMMIT();
    STAGE_IDX(p + GRID, idxs[1]);
    __syncthreads();
    PRODUCE(1, idxs[1]);
    CP_COMMIT();
    STAGE_IDX(p + 2 * GRID, idxs[2]);

    // private prime: offsets + chunk0 of p into buffer X
    unsigned pvo0 = (unsigned)pos_v[p * 10 + w * 2 + 0] * ROWBYTES;
    unsigned pvo1 = (unsigned)pos_v[p * 10 + w * 2 + 1] * ROWBYTES;
    float4 Xa0, Xa1, Xb0, Xb1;
    float4 Ya0, Ya1, Yb0, Yb1;
    AB_LOAD(X, jb0);
    __syncthreads();            // idxs[2] visible before first loop PRODUCE

    // ---- main loop, 2x unrolled for X/Y role rotation ----
    while (true) {
        ITER(X, Y);
        if (p >= NPOS) break;
        ITER(Y, X);
        if (p >= NPOS) break;
    }

    // ---- block reduction ----
#pragma unroll
    for (int off = 16; off; off >>= 1)
        acc_loss += __shfl_xor_sync(0xffffffffu, acc_loss, off);
    if (lane == 0) wloss[w] = acc_loss;
    __syncthreads();

    if (tid == 0) {
        float s = wloss[0] + wloss[1] + wloss[2] + wloss[3] + wloss[4];
        g_partial[blockIdx.x] = s;
        __threadfence();
        unsigned t = atomicAdd(&g_ticket, 1u);
        amLast = (t == GRID - 1);
    }
    __syncthreads();

    // ---- last block: deterministic fixed-order final sum ----
    if (amLast) {
        __shared__ float fs[THREADS];
        float v = 0.f;
        for (int i = tid; i < GRID; i += THREADS)
            v += __ldcg(&g_partial[i]);
        fs[tid] = v;
        __syncthreads();
#pragma unroll
        for (int st = 128; st; st >>= 1) {
            if (tid < st && tid + st < THREADS)
                fs[tid] += fs[tid + st];
            __syncthreads();
        }
        if (tid == 0) {
            out[0] = fs[0];
            g_ticket = 0;            // reset for next graph replay
            __threadfence();
        }
    }
}

extern "C" void kernel_launch(void* const* d_in, const int* in_sizes, int n_in,
                              void* d_out, int out_size)
{
    const int*   pos_u  = (const int*)  d_in[0];
    const int*   pos_v  = (const int*)  d_in[1];
    const int*   info_v = (const int*)  d_in[2];
    const float* W_in   = (const float*)d_in[3];
    const float* W_out  = (const float*)d_in[4];
    const float* cmask  = (const float*)d_in[5];
    const float* sigm   = (const float*)d_in[6];
    const float* smask  = (const float*)d_in[7];

    hg2vec_fused<<<GRID, THREADS>>>(pos_u, pos_v, info_v, W_in, W_out,
                                    cmask, sigm, smask, (float*)d_out);
}

// round 12
// speedup vs baseline: 1.1812x; 1.1812x over previous
#include <cuda_runtime.h>
#include <math.h>

// HG2Vec fused loss, v12: minimal-duplication decomposition.
// Warp per (position, context-half): each warp computes 5 contexts x (1 score
// + 6 info) = 35 dot products, reading t + f[0..5] + 5a + 5b = 17 rows ONCE.
// Per position: 34 row-reads through l1tex vs 55 in v6/v10 (the t/f rows were
// re-read 5x; L1 hits still consume the 128B/cyc return port, which wavefront
// accounting shows is co-roofline with DRAM at the ~87us plateau).
//  - 35 accumulators; a/b pair rotated (load c+1 before FMAs of c, full unroll)
//  - scattered 32-value warp reduction (62 shfl) for {sc0,sc1,ai[0..29]} +
//    classic butterfly for sc2..4 (15 shfl); loss terms evaluated lane-parallel
//  - next-iteration indices loaded into dead offset regs before the reduction
//  - __launch_bounds__(128,4): reg cap 128 (est ~106, no spill), 16 warps/SM
//  - grid 592 = 148 SMs * 4 CTAs, persistent; 4 warps/CTA = 2 positions/iter
//  - last-block-done deterministic reduction, ticket self-resets (graph-safe)

#define ROWBYTES  1200u
#define NPOS      16384
#define NPAIR     8192            // 2 positions per CTA iteration
#define GRID      592             // 148 SMs * 4 resident CTAs
#define THREADS   128             // 4 warps: 2 positions x 2 c-halves

__device__ float        g_partial[GRID];
__device__ unsigned int g_ticket = 0;

__global__ __launch_bounds__(THREADS, 4) void hg2vec_fused(
    const int*   __restrict__ pos_u,
    const int*   __restrict__ pos_v,
    const int*   __restrict__ info_v,
    const float* __restrict__ W_in,
    const float* __restrict__ W_out,
    const float* __restrict__ cmask,
    const float* __restrict__ sig_mask,
    const float* __restrict__ score_mask,
    float*       __restrict__ out)
{
    __shared__ float wloss[4];
    __shared__ bool  amLast;

    const int tid  = threadIdx.x;
    const int w    = tid >> 5;
    const int lane = tid & 31;
    const int grp  = w & 1;        // context half: c = grp*5 .. grp*5+4
    const int wpos = w >> 1;       // which of the 2 positions this iteration

    const char* __restrict__ Win_b  = (const char*)W_in;
    const char* __restrict__ Wout_b = (const char*)W_out;

    // ---- per-lane term coefficients for the 32-value scatter ----
    // lane 0,1 -> score c = grp*5 + lane ; lane 2..31 -> info k = lane-2,
    // c_local = k/6, i = k%6
    float t_pre = 1.f, t_sgn = 1.f, t_wt = 1.f;
    if (lane < 2) {
        t_pre = cmask[grp * 5 + lane];
    } else {
        const int i = (lane - 2) % 6;
        t_sgn = sig_mask[i];
        t_wt  = score_mask[i];
    }
    // aux coefficients for classically-reduced sc2..4 (evaluated on lanes 4..6)
    float a_pre = 0.f, a_wt = 0.f;
    if (lane >= 4 && lane < 7) {
        a_pre = cmask[grp * 5 + 2 + (lane - 4)];
        a_wt  = 1.f;
    }

    float acc_loss = 0.f;

    int pp = blockIdx.x;

    // ---- prime offsets for the first position ----
    unsigned puo;
    unsigned pvo[5], ivo[6];
    {
        const int p = pp * 2 + wpos;
        puo = (unsigned)pos_u[p] * ROWBYTES;
#pragma unroll
        for (int c = 0; c < 5; c++)
            pvo[c] = (unsigned)pos_v[p * 10 + grp * 5 + c] * ROWBYTES;
#pragma unroll
        for (int i = 0; i < 6; i++)
            ivo[i] = (unsigned)info_v[p * 6 + i] * ROWBYTES;
    }

    while (pp < NPAIR) {
        const int pn = pp + GRID;

        // ---- 35 accumulators ----
        float sc[5];
        float ai[30];
#pragma unroll
        for (int c = 0; c < 5; c++) sc[c] = 0.f;
#pragma unroll
        for (int q = 0; q < 30; q++) ai[q] = 0.f;

        // ---- 3 d-chunks; each row read once by this warp ----
#pragma unroll
        for (int jj = 0; jj < 3; jj++) {
            const int j = lane + jj * 32;
            if (j < 75) {
                const unsigned jb = (unsigned)j * 16u;
                const float4 t4 = *(const float4*)(Wout_b + puo + jb);
                float4 f4[6];
#pragma unroll
                for (int i = 0; i < 6; i++)
                    f4[i] = *(const float4*)(Win_b + ivo[i] + jb);

                // a/b pair rotation: load c+1 before consuming c
                float4 ca = *(const float4*)(Win_b  + pvo[0] + jb);
                float4 cb = *(const float4*)(Wout_b + pvo[0] + jb);
#pragma unroll
                for (int c = 0; c < 5; c++) {
                    float4 na, nb;
                    if (c < 4) {
                        na = *(const float4*)(Win_b  + pvo[c + 1] + jb);
                        nb = *(const float4*)(Wout_b + pvo[c + 1] + jb);
                    }
                    sc[c] += ca.x * t4.x + ca.y * t4.y
                           + ca.z * t4.z + ca.w * t4.w;
#pragma unroll
                    for (int i = 0; i < 6; i++) {
                        ai[c * 6 + i] += cb.x * f4[i].x + cb.y * f4[i].y
                                       + cb.z * f4[i].z + cb.w * f4[i].w;
                    }
                    if (c < 4) { ca = na; cb = nb; }
                }
            }
        }

        // ---- offsets dead: load next iteration's indices now (overlaps
        //      the shuffle reduction below; idx arrays are L2-resident) ----
        {
            const int pq = (pn < NPAIR) ? pn : 0;
            const int p2 = pq * 2 + wpos;
            puo = (unsigned)pos_u[p2] * ROWBYTES;
#pragma unroll
            for (int c = 0; c < 5; c++)
                pvo[c] = (unsigned)pos_v[p2 * 10 + grp * 5 + c] * ROWBYTES;
#pragma unroll
            for (int i = 0; i < 6; i++)
                ivo[i] = (unsigned)info_v[p2 * 6 + i] * ROWBYTES;
        }

        // ---- scattered 32-value warp reduction ----
        // x[0..31] = {sc0, sc1, ai[0..29]}; after 5 select-rounds, lane L
        // holds the full warp-sum of value L.
        {
            float v0[16];
            {
                float a, b;
                a = sc[0]  + __shfl_xor_sync(0xffffffffu, sc[0],  16);
                b = ai[14] + __shfl_xor_sync(0xffffffffu, ai[14], 16);
                v0[0] = (lane & 16) ? b : a;
                a = sc[1]  + __shfl_xor_sync(0xffffffffu, sc[1],  16);
                b = ai[15] + __shfl_xor_sync(0xffffffffu, ai[15], 16);
                v0[1] = (lane & 16) ? b : a;
#pragma unroll
                for (int q = 2; q < 16; q++) {
                    a = ai[q - 2]  + __shfl_xor_sync(0xffffffffu, ai[q - 2],  16);
                    b = ai[q + 14] + __shfl_xor_sync(0xffffffffu, ai[q + 14], 16);
                    v0[q] = (lane & 16) ? b : a;
                }
            }
            float v1[8];
#pragma unroll
            for (int q = 0; q < 8; q++) {
                const float a = v0[q]     + __shfl_xor_sync(0xffffffffu, v0[q],     8);
                const float b = v0[q + 8] + __shfl_xor_sync(0xffffffffu, v0[q + 8], 8);
                v1[q] = (lane & 8) ? b : a;
            }
            float v2[4];
#pragma unroll
            for (int q = 0; q < 4; q++) {
                const float a = v1[q]     + __shfl_xor_sync(0xffffffffu, v1[q],     4);
                const float b = v1[q + 4] + __shfl_xor_sync(0xffffffffu, v1[q + 4], 4);
                v2[q] = (lane & 4) ? b : a;
            }
            float v3[2];
#pragma unroll
            for (int q = 0; q < 2; q++) {
                const float a = v2[q]     + __shfl_xor_sync(0xffffffffu, v2[q],     2);
                const float b = v2[q + 2] + __shfl_xor_sync(0xffffffffu, v2[q + 2], 2);
                v3[q] = (lane & 2) ? b : a;
            }
            float v4;
            {
                const float a = v3[0] + __shfl_xor_sync(0xffffffffu, v3[0], 1);
                const float b = v3[1] + __shfl_xor_sync(0xffffffffu, v3[1], 1);
                v4 = (lane & 1) ? b : a;
            }

            // classic butterfly for the 3 remaining score sums
#pragma unroll
            for (int off = 16; off; off >>= 1) {
                sc[2] += __shfl_xor_sync(0xffffffffu, sc[2], off);
                sc[3] += __shfl_xor_sync(0xffffffffu, sc[3], off);
                sc[4] += __shfl_xor_sync(0xffffffffu, sc[4], off);
            }

            // ---- lane-parallel loss terms ----
            const float x = fminf(fmaxf(v4 * t_pre, -10.f), 10.f) * t_sgn;
            acc_loss += __logf(1.f + __expf(-x)) * t_wt;

            const float sa = (lane == 4) ? sc[2] : ((lane == 5) ? sc[3] : sc[4]);
            const float xa = fminf(fmaxf(sa * a_pre, -10.f), 10.f);
            acc_loss += __logf(1.f + __expf(-xa)) * a_wt;
        }

        pp = pn;
    }

    // ---- block reduction ----
#pragma unroll
    for (int off = 16; off; off >>= 1)
        acc_loss += __shfl_xor_sync(0xffffffffu, acc_loss, off);
    if (lane == 0) wloss[w] = acc_loss;
    __syncthreads();

    if (tid == 0) {
        float s = wloss[0] + wloss[1] + wloss[2] + wloss[3];
        g_partial[blockIdx.x] = s;
        __threadfence();
        unsigned t = atomicAdd(&g_ticket, 1u);
        amLast = (t == GRID - 1);
    }
    __syncthreads();

    // ---- last block: deterministic fixed-order final sum ----
    if (amLast) {
        __shared__ float fs[THREADS];
        float v = 0.f;
        for (int i = tid; i < GRID; i += THREADS)
            v += __ldcg(&g_partial[i]);
        fs[tid] = v;
        __syncthreads();
#pragma unroll
        for (int st = THREADS / 2; st; st >>= 1) {
            if (tid < st) fs[tid] += fs[tid + st];
            __syncthreads();
        }
        if (tid == 0) {
            out[0] = fs[0];
            g_ticket = 0;            // reset for next graph replay
            __threadfence();
        }
    }
}

extern "C" void kernel_launch(void* const* d_in, const int* in_sizes, int n_in,
                              void* d_out, int out_size)
{
    const int*   pos_u  = (const int*)  d_in[0];
    const int*   pos_v  = (const int*)  d_in[1];
    const int*   info_v = (const int*)  d_in[2];
    const float* W_in   = (const float*)d_in[3];
    const float* W_out  = (const float*)d_in[4];
    const float* cmask  = (const float*)d_in[5];
    const float* sigm   = (const float*)d_in[6];
    const float* smask  = (const float*)d_in[7];

    hg2vec_fused<<<GRID, THREADS>>>(pos_u, pos_v, info_v, W_in, W_out,
                                    cmask, sigm, smask, (float*)d_out);
}